// round 1
// baseline (speedup 1.0000x reference)
#include <cuda_runtime.h>
#include <math.h>

#define B_  2
#define N_  1024
#define T_  8
#define D_  128
#define H_  4
#define E_  8192
#define EP_ 9216          // E + N self loops
#define M_  16384         // B*N*T rows

// ---------------- scratch (device globals; no allocation allowed) ----------
__device__ float g_xl[M_ * 512];
__device__ float g_xr[M_ * 512];
__device__ float g_logits[EP_ * B_ * T_ * H_];   // (e,b,t,h) -> later p
__device__ float g_mx[B_ * N_ * T_ * H_];
__device__ float g_ssum[B_ * N_ * T_ * H_];
__device__ float g_agg[M_ * D_];
__device__ float g_qkv[M_ * 384];
__device__ float g_attno[M_ * D_];
__device__ float g_oproj[M_ * D_];
__device__ float g_x1[M_ * D_];
__device__ float g_hid[M_ * 512];
__device__ float g_f2[M_ * D_];
__device__ float g_cat[M_ * 256];   // [:,0:128]=x_sp  [:,128:256]=x_tp
__device__ float g_gate[M_ * D_];

// ---------------- helpers ---------------------------------------------------
__device__ __forceinline__ float warp_sum(float v) {
#pragma unroll
    for (int o = 16; o; o >>= 1) v += __shfl_xor_sync(0xFFFFFFFFu, v, o);
    return v;
}

__device__ __forceinline__ void atomicMaxFloat(float* addr, float val) {
    int old = __float_as_int(*addr);
    while (__int_as_float(old) < val) {
        int assumed = old;
        old = atomicCAS((int*)addr, assumed, __float_as_int(val));
        if (old == assumed) break;
    }
}

// ---------------- init scratch (must run every replay) ---------------------
__global__ void k_init() {
    int i = blockIdx.x * blockDim.x + threadIdx.x;
    if (i < B_ * N_ * T_ * H_) { g_mx[i] = -INFINITY; g_ssum[i] = 0.f; }
    if (i < M_ * D_) g_agg[i] = 0.f;
}

// ---------------- generic fp32 SGEMM: C = A(MxK) * B(KxN) [+bias][+act] ----
// mode: 0 none, 1 bias, 2 bias+gelu(exact), 3 bias+sigmoid
__global__ void sgemm(const float* __restrict__ A, const float* __restrict__ Bm,
                      const float* __restrict__ bias, float* __restrict__ C,
                      int M, int N, int K, int mode) {
    __shared__ float As[16][64];
    __shared__ float Bs[16][64];
    int tid = threadIdx.x;                 // 256 threads
    int tx = tid & 15, ty = tid >> 4;      // 16x16 threads, 4x4 micro tile
    int rowBase = blockIdx.y * 64;
    int colBase = blockIdx.x * 64;

    float acc[4][4];
#pragma unroll
    for (int i = 0; i < 4; i++)
#pragma unroll
        for (int j = 0; j < 4; j++) acc[i][j] = 0.f;

    int ra = tid >> 2;               // 0..63
    int ca = (tid & 3) << 2;         // 0,4,8,12
    int rb = tid >> 4;               // 0..15
    int cb = (tid & 15) << 2;        // 0..60

    for (int kt = 0; kt < K; kt += 16) {
        float4 av = *(const float4*)&A[(size_t)(rowBase + ra) * K + kt + ca];
        As[ca + 0][ra] = av.x; As[ca + 1][ra] = av.y;
        As[ca + 2][ra] = av.z; As[ca + 3][ra] = av.w;
        *(float4*)&Bs[rb][cb] =
            *(const float4*)&Bm[(size_t)(kt + rb) * N + colBase + cb];
        __syncthreads();
#pragma unroll
        for (int k = 0; k < 16; k++) {
            float4 a = *(float4*)&As[k][ty << 2];
            float4 b = *(float4*)&Bs[k][tx << 2];
            float ar[4] = {a.x, a.y, a.z, a.w};
            float br[4] = {b.x, b.y, b.z, b.w};
#pragma unroll
            for (int i = 0; i < 4; i++)
#pragma unroll
                for (int j = 0; j < 4; j++) acc[i][j] += ar[i] * br[j];
        }
        __syncthreads();
    }

    int col = colBase + (tx << 2);
    float4 bv = make_float4(0.f, 0.f, 0.f, 0.f);
    if (mode > 0) bv = *(const float4*)&bias[col];
#pragma unroll
    for (int i = 0; i < 4; i++) {
        int row = rowBase + (ty << 2) + i;
        float v[4];
#pragma unroll
        for (int j = 0; j < 4; j++) v[j] = acc[i][j];
        v[0] += bv.x; v[1] += bv.y; v[2] += bv.z; v[3] += bv.w;
        if (mode == 2) {
#pragma unroll
            for (int j = 0; j < 4; j++)
                v[j] = 0.5f * v[j] * (1.f + erff(v[j] * 0.70710678118654752f));
        } else if (mode == 3) {
#pragma unroll
            for (int j = 0; j < 4; j++)
                v[j] = 1.f / (1.f + __expf(-v[j]));
        }
        float4 o = make_float4(v[0], v[1], v[2], v[3]);
        *(float4*)&C[(size_t)row * N + col] = o;
    }
}

// ---------------- GAT: logits + segment max --------------------------------
__global__ void k_logits(const int* __restrict__ edges,
                         const float* __restrict__ att) {
    int w = (blockIdx.x * blockDim.x + threadIdx.x) >> 5;
    int lane = threadIdx.x & 31;
    if (w >= EP_ * B_ * T_) return;
    int e = w / (B_ * T_);
    int bt = w % (B_ * T_);
    int b = bt >> 3, t = bt & 7;
    int s, dn;
    if (e < E_) { s = edges[e]; dn = edges[E_ + e]; } else { s = dn = e - E_; }

    const float4* xl4 = (const float4*)(g_xl + (((size_t)(b * N_ + s)  * T_ + t) * 512));
    const float4* xr4 = (const float4*)(g_xr + (((size_t)(b * N_ + dn) * T_ + t) * 512));
    const float4* at4 = (const float4*)att;

#pragma unroll
    for (int h = 0; h < H_; h++) {
        float4 a = xl4[h * 32 + lane];
        float4 c = xr4[h * 32 + lane];
        float4 wv = at4[h * 32 + lane];
        float v0 = a.x + c.x; v0 = v0 > 0.f ? v0 : 0.2f * v0;
        float v1 = a.y + c.y; v1 = v1 > 0.f ? v1 : 0.2f * v1;
        float v2 = a.z + c.z; v2 = v2 > 0.f ? v2 : 0.2f * v2;
        float v3 = a.w + c.w; v3 = v3 > 0.f ? v3 : 0.2f * v3;
        float sum = wv.x * v0 + wv.y * v1 + wv.z * v2 + wv.w * v3;
        sum = warp_sum(sum);
        if (lane == 0) {
            g_logits[((size_t)(e * B_ + b) * T_ + t) * H_ + h] = sum;
            atomicMaxFloat(&g_mx[((b * N_ + dn) * T_ + t) * H_ + h], sum);
        }
    }
}

// ---------------- GAT: p = exp(logit - mx), segment sum --------------------
__global__ void k_p(const int* __restrict__ edges) {
    int i = blockIdx.x * blockDim.x + threadIdx.x;
    if (i >= EP_ * B_ * T_ * H_) return;
    int h = i & 3;
    int r = i >> 2;
    int t = r & 7; r >>= 3;
    int b = r & 1;
    int e = r >> 1;
    int dn = (e < E_) ? edges[E_ + e] : e - E_;
    int mi = ((b * N_ + dn) * T_ + t) * H_ + h;
    float p = __expf(g_logits[i] - g_mx[mi]);
    g_logits[i] = p;
    atomicAdd(&g_ssum[mi], p);
}

// ---------------- GAT: aggregate messages (mean over heads fused) ----------
__global__ void k_agg(const int* __restrict__ edges) {
    int w = (blockIdx.x * blockDim.x + threadIdx.x) >> 5;
    int lane = threadIdx.x & 31;
    if (w >= EP_ * B_ * T_) return;
    int e = w / (B_ * T_);
    int bt = w % (B_ * T_);
    int b = bt >> 3, t = bt & 7;
    int s, dn;
    if (e < E_) { s = edges[e]; dn = edges[E_ + e]; } else { s = dn = e - E_; }

    const float4* xl4 = (const float4*)(g_xl + (((size_t)(b * N_ + s) * T_ + t) * 512));
    size_t lbase = ((size_t)(e * B_ + b) * T_ + t) * H_;
    int mbase = ((b * N_ + dn) * T_ + t) * H_;

    float4 acc = make_float4(0.f, 0.f, 0.f, 0.f);
#pragma unroll
    for (int h = 0; h < H_; h++) {
        float alpha = g_logits[lbase + h] / g_ssum[mbase + h];
        alpha *= 0.25f;   // mean over H heads
        float4 a = xl4[h * 32 + lane];
        acc.x += alpha * a.x; acc.y += alpha * a.y;
        acc.z += alpha * a.z; acc.w += alpha * a.w;
    }
    float* dp = g_agg + ((size_t)(b * N_ + dn) * T_ + t) * D_ + lane * 4;
    atomicAdd(dp + 0, acc.x);
    atomicAdd(dp + 1, acc.y);
    atomicAdd(dp + 2, acc.z);
    atomicAdd(dp + 3, acc.w);
}

// ---------------- LayerNorm helpers (one warp per row of 128) --------------
__device__ __forceinline__ void ln_store(float4 v, const float* g, const float* b,
                                         float* out, int lane) {
    float mean = warp_sum(v.x + v.y + v.z + v.w) * (1.f / 128.f);
    float4 c = make_float4(v.x - mean, v.y - mean, v.z - mean, v.w - mean);
    float var = warp_sum(c.x * c.x + c.y * c.y + c.z * c.z + c.w * c.w) * (1.f / 128.f);
    float rs = rsqrtf(var + 1e-5f);
    float4 gv = *(const float4*)&g[lane * 4];
    float4 bv = *(const float4*)&b[lane * 4];
    float4 o = make_float4(c.x * rs * gv.x + bv.x, c.y * rs * gv.y + bv.y,
                           c.z * rs * gv.z + bv.z, c.w * rs * gv.w + bv.w);
    *(float4*)&out[lane * 4] = o;
}

__global__ void k_lns(const float* __restrict__ gat_b,
                      const float* __restrict__ g, const float* __restrict__ b) {
    int row = (blockIdx.x * blockDim.x + threadIdx.x) >> 5;
    int lane = threadIdx.x & 31;
    if (row >= M_) return;
    float4 v = *(const float4*)&g_agg[(size_t)row * D_ + lane * 4];
    float4 gb = *(const float4*)&gat_b[lane * 4];
    v.x += gb.x; v.y += gb.y; v.z += gb.z; v.w += gb.w;
    ln_store(v, g, b, &g_cat[(size_t)row * 256], lane);
}

__global__ void k_lnt1(const float* __restrict__ x,
                       const float* __restrict__ g, const float* __restrict__ b) {
    int row = (blockIdx.x * blockDim.x + threadIdx.x) >> 5;
    int lane = threadIdx.x & 31;
    if (row >= M_) return;
    float4 v  = *(const float4*)&x[(size_t)row * D_ + lane * 4];
    float4 v2 = *(const float4*)&g_oproj[(size_t)row * D_ + lane * 4];
    v.x += v2.x; v.y += v2.y; v.z += v2.z; v.w += v2.w;
    ln_store(v, g, b, &g_x1[(size_t)row * D_], lane);
}

__global__ void k_lnt2(const float* __restrict__ g, const float* __restrict__ b) {
    int row = (blockIdx.x * blockDim.x + threadIdx.x) >> 5;
    int lane = threadIdx.x & 31;
    if (row >= M_) return;
    float4 v  = *(const float4*)&g_x1[(size_t)row * D_ + lane * 4];
    float4 v2 = *(const float4*)&g_f2[(size_t)row * D_ + lane * 4];
    v.x += v2.x; v.y += v2.y; v.z += v2.z; v.w += v2.w;
    ln_store(v, g, b, &g_cat[(size_t)row * 256 + 128], lane);
}

__global__ void k_final(const float* __restrict__ x,
                        const float* __restrict__ g, const float* __restrict__ b,
                        float* __restrict__ out) {
    int row = (blockIdx.x * blockDim.x + threadIdx.x) >> 5;
    int lane = threadIdx.x & 31;
    if (row >= M_) return;
    float4 xsp = *(const float4*)&g_cat[(size_t)row * 256 + lane * 4];
    float4 xtp = *(const float4*)&g_cat[(size_t)row * 256 + 128 + lane * 4];
    float4 gt  = *(const float4*)&g_gate[(size_t)row * D_ + lane * 4];
    float4 xv  = *(const float4*)&x[(size_t)row * D_ + lane * 4];
    float4 v = make_float4(gt.x * xsp.x + (1.f - gt.x) * xtp.x + xv.x,
                           gt.y * xsp.y + (1.f - gt.y) * xtp.y + xv.y,
                           gt.z * xsp.z + (1.f - gt.z) * xtp.z + xv.z,
                           gt.w * xsp.w + (1.f - gt.w) * xtp.w + xv.w);
    ln_store(v, g, b, &out[(size_t)row * D_], lane);
}

// ---------------- temporal attention: one warp per (bn, h) -----------------
__global__ void k_attn() {
    int w = blockIdx.x * 4 + (threadIdx.x >> 5);
    int lane = threadIdx.x & 31;
    if (w >= (B_ * N_) * H_) return;
    int bn = w >> 2;
    int h = w & 3;

    float q[8], k[8], v[8];
#pragma unroll
    for (int t = 0; t < 8; t++) {
        size_t base = ((size_t)bn * 8 + t) * 384 + h * 32 + lane;
        q[t] = g_qkv[base];
        k[t] = g_qkv[base + 128];
        v[t] = g_qkv[base + 256];
    }
    const float scale = 0.17677669529663687f;  // 1/sqrt(32)
#pragma unroll
    for (int t = 0; t < 8; t++) {
        float sc[8];
#pragma unroll
        for (int s = 0; s < 8; s++) sc[s] = warp_sum(q[t] * k[s]) * scale;
        float mx = sc[0];
#pragma unroll
        for (int s = 1; s < 8; s++) mx = fmaxf(mx, sc[s]);
        float den = 0.f;
#pragma unroll
        for (int s = 0; s < 8; s++) { sc[s] = __expf(sc[s] - mx); den += sc[s]; }
        float inv = 1.f / den;
        float o = 0.f;
#pragma unroll
        for (int s = 0; s < 8; s++) o += sc[s] * v[s];
        o *= inv;
        g_attno[((size_t)bn * 8 + t) * D_ + h * 32 + lane] = o;
    }
}

// ---------------- launch ----------------------------------------------------
extern "C" void kernel_launch(void* const* d_in, const int* in_sizes, int n_in,
                              void* d_out, int out_size) {
    const float* x      = (const float*)d_in[0];
    const int*   edges  = (const int*)  d_in[1];
    const float* gat_wl = (const float*)d_in[2];
    const float* gat_wr = (const float*)d_in[3];
    const float* gat_att= (const float*)d_in[4];
    const float* gat_b  = (const float*)d_in[5];
    const float* in_w   = (const float*)d_in[6];
    const float* in_b   = (const float*)d_in[7];
    const float* out_w  = (const float*)d_in[8];
    const float* out_b  = (const float*)d_in[9];
    const float* ffn_w1 = (const float*)d_in[10];
    const float* ffn_b1 = (const float*)d_in[11];
    const float* ffn_w2 = (const float*)d_in[12];
    const float* ffn_b2 = (const float*)d_in[13];
    const float* fus_w  = (const float*)d_in[14];
    const float* fus_b  = (const float*)d_in[15];
    const float* lns_g  = (const float*)d_in[16];
    const float* lns_b  = (const float*)d_in[17];
    const float* lnt1_g = (const float*)d_in[18];
    const float* lnt1_b = (const float*)d_in[19];
    const float* lnt2_g = (const float*)d_in[20];
    const float* lnt2_b = (const float*)d_in[21];
    const float* lnf_g  = (const float*)d_in[22];
    const float* lnf_b  = (const float*)d_in[23];
    float* out = (float*)d_out;

    float *p_xl, *p_xr, *p_qkv, *p_attno, *p_oproj, *p_x1, *p_hid, *p_f2, *p_cat, *p_gate;
    cudaGetSymbolAddress((void**)&p_xl,    g_xl);
    cudaGetSymbolAddress((void**)&p_xr,    g_xr);
    cudaGetSymbolAddress((void**)&p_qkv,   g_qkv);
    cudaGetSymbolAddress((void**)&p_attno, g_attno);
    cudaGetSymbolAddress((void**)&p_oproj, g_oproj);
    cudaGetSymbolAddress((void**)&p_x1,    g_x1);
    cudaGetSymbolAddress((void**)&p_hid,   g_hid);
    cudaGetSymbolAddress((void**)&p_f2,    g_f2);
    cudaGetSymbolAddress((void**)&p_cat,   g_cat);
    cudaGetSymbolAddress((void**)&p_gate,  g_gate);

    // 0. init scratch (mx/ssum/agg) — must happen on every replay
    k_init<<<(M_ * D_) / 256, 256>>>();

    // 1. spatial projections xl = x@Wl, xr = x@Wr : (16384,128)@(128,512)
    sgemm<<<dim3(512 / 64, M_ / 64), 256>>>(x, gat_wl, nullptr, p_xl, M_, 512, 128, 0);
    sgemm<<<dim3(512 / 64, M_ / 64), 256>>>(x, gat_wr, nullptr, p_xr, M_, 512, 128, 0);

    // 2. GAT edge softmax + aggregation
    k_logits<<<(EP_ * B_ * T_) / 8, 256>>>(edges, gat_att);
    k_p<<<(EP_ * B_ * T_ * H_) / 256, 256>>>(edges);
    k_agg<<<(EP_ * B_ * T_) / 8, 256>>>(edges);
    k_lns<<<M_ / 8, 256>>>(gat_b, lns_g, lns_b);   // -> g_cat[:, :128]

    // 3. temporal attention
    sgemm<<<dim3(384 / 64, M_ / 64), 256>>>(x, in_w, in_b, p_qkv, M_, 384, 128, 1);
    k_attn<<<(B_ * N_ * H_) / 4, 128>>>();
    sgemm<<<dim3(128 / 64, M_ / 64), 256>>>(p_attno, out_w, out_b, p_oproj, M_, 128, 128, 1);
    k_lnt1<<<M_ / 8, 256>>>(x, lnt1_g, lnt1_b);

    // 4. FFN
    sgemm<<<dim3(512 / 64, M_ / 64), 256>>>(p_x1, ffn_w1, ffn_b1, p_hid, M_, 512, 128, 2);
    sgemm<<<dim3(128 / 64, M_ / 64), 256>>>(p_hid, ffn_w2, ffn_b2, p_f2, M_, 128, 512, 1);
    k_lnt2<<<M_ / 8, 256>>>(lnt2_g, lnt2_b);       // -> g_cat[:, 128:]

    // 5. gated fusion + final LN
    sgemm<<<dim3(128 / 64, M_ / 64), 256>>>(p_cat, fus_w, fus_b, p_gate, M_, 128, 256, 3);
    k_final<<<M_ / 8, 256>>>(x, lnf_g, lnf_b, out);
}